// round 1
// baseline (speedup 1.0000x reference)
#include <cuda_runtime.h>

// Problem-size maxima (setup_inputs: N=20000, E=320000)
#define NMAX_NODES 20000
#define EMAX_EDGES 320000

// Scratch (static device globals; no allocation allowed)
__device__ int g_count[NMAX_NODES];
__device__ int g_off[NMAX_NODES + 1];
__device__ int g_cur[NMAX_NODES];
__device__ int g_sorted[EMAX_EDGES];

// ---------------------------------------------------------------------------
// 1) zero histogram
__global__ void k_zero(int N) {
    int t = blockIdx.x * blockDim.x + threadIdx.x;
    if (t < N) g_count[t] = 0;
}

// 2) histogram of destination node i
__global__ void k_hist(const int* __restrict__ eidx, int E) {
    int e = blockIdx.x * blockDim.x + threadIdx.x;
    if (e < E) atomicAdd(&g_count[eidx[e]], 1);
}

// 3) single-block exclusive scan over counts -> offsets (+cursor copy)
__global__ void k_scan(int N, int E) {
    __shared__ int sh[1024];
    int t = threadIdx.x;
    int chunk = (N + 1023) >> 10;
    int b = t * chunk;
    int en = min(b + chunk, N);
    int s = 0;
    for (int k = b; k < en; k++) s += g_count[k];
    sh[t] = s;
    __syncthreads();
    for (int off = 1; off < 1024; off <<= 1) {
        int tmp = (t >= off) ? sh[t - off] : 0;
        __syncthreads();
        sh[t] += tmp;
        __syncthreads();
    }
    int base = sh[t] - s;  // exclusive prefix
    for (int k = b; k < en; k++) {
        g_off[k] = base;
        g_cur[k] = base;
        base += g_count[k];
    }
    if (t == 1023) g_off[N] = sh[1023];
}

// 4) scatter edge ids into per-node contiguous lists
__global__ void k_scatter(const int* __restrict__ eidx, int E) {
    int e = blockIdx.x * blockDim.x + threadIdx.x;
    if (e < E) {
        int p = atomicAdd(&g_cur[eidx[e]], 1);
        g_sorted[p] = e;
    }
}

// ---------------------------------------------------------------------------
// 5) main: one warp per node. Lane r owns accumulator column c[m][r], m=0..15.
//    Then Gram matrices per l via warp shuffles; coalesced output stores.
__global__ void __launch_bounds__(256) k_main(
    const float* __restrict__ pos,
    const float* __restrict__ cells,
    const int*   __restrict__ species,
    const int*   __restrict__ eidx,
    const int*   __restrict__ shifts,
    const float* __restrict__ embed,
    const float* __restrict__ mu,
    const float* __restrict__ sig,
    float* __restrict__ out,
    int N, int E)
{
    int gwarp = (blockIdx.x * blockDim.x + threadIdx.x) >> 5;
    int lane  = threadIdx.x & 31;
    if (gwarp >= N) return;
    const int node = gwarp;

    float acc[16];
#pragma unroll
    for (int m = 0; m < 16; m++) acc[m] = 0.0f;

    const int   p_lane = lane >> 3;   // pseudo index 0..3
    const int   n_lane = lane & 7;    // radial index 0..7
    const float mu_l   = mu[n_lane];
    const float sg     = sig[0];
    const float negInv = -1.0f / (2.0f * sg * sg);

    float C[9];
#pragma unroll
    for (int k = 0; k < 9; k++) C[k] = cells[k];

    const float pix = pos[3 * node + 0];
    const float piy = pos[3 * node + 1];
    const float piz = pos[3 * node + 2];

    const int st = g_off[node];
    const int en = g_off[node + 1];

    for (int idx = st; idx < en; idx++) {
        int e = g_sorted[idx];
        int j = eidx[E + e];

        float pjx = pos[3 * j + 0];
        float pjy = pos[3 * j + 1];
        float pjz = pos[3 * j + 2];

        float s0 = (float)shifts[3 * e + 0];
        float s1 = (float)shifts[3 * e + 1];
        float s2 = (float)shifts[3 * e + 2];

        // rij = pos[j] - pos[i] + s @ cells[0]
        float dx = pjx - pix + s0 * C[0] + s1 * C[3] + s2 * C[6];
        float dy = pjy - piy + s0 * C[1] + s1 * C[4] + s2 * C[7];
        float dz = pjz - piz + s0 * C[2] + s1 * C[5] + s2 * C[8];

        float r2   = dx * dx + dy * dy + dz * dz + 1e-12f;
        float rinv = rsqrtf(r2);
        float r    = r2 * rinv;
        if (r >= 5.0f) continue;  // fcut == 0, zero contribution (warp-uniform)

        float x = dx * rinv, y = dy * rinv, z = dz * rinv;

        float fc = 0.5f * (__cosf(0.6283185307f * r) + 1.0f);

        // per-lane radial * embed -> w[lane]
        float d  = r - mu_l;
        float Rn = __expf(d * d * negInv) * fc;
        int   sp = species[j];
        float w  = embed[sp * 4 + p_lane] * Rn;

        float x2 = x * x, y2 = y * y, z2 = z * z;
        float Y[16];
        Y[0]  = 0.28209479177387814f;
        Y[1]  = 0.4886025119029199f * y;
        Y[2]  = 0.4886025119029199f * z;
        Y[3]  = 0.4886025119029199f * x;
        Y[4]  = 1.0925484305920792f * x * y;
        Y[5]  = 1.0925484305920792f * y * z;
        Y[6]  = 0.31539156525252005f * (3.0f * z2 - 1.0f);
        Y[7]  = 1.0925484305920792f * x * z;
        Y[8]  = 0.5462742152960396f * (x2 - y2);
        Y[9]  = 0.5900435899266435f * y * (3.0f * x2 - y2);
        Y[10] = 2.890611442640554f  * x * y * z;
        Y[11] = 0.4570457994644658f * y * (5.0f * z2 - 1.0f);
        Y[12] = 0.3731763325901154f * z * (5.0f * z2 - 3.0f);
        Y[13] = 0.4570457994644658f * x * (5.0f * z2 - 1.0f);
        Y[14] = 1.445305721320277f  * z * (x2 - y2);
        Y[15] = 0.5900435899266435f * x * (x2 - 3.0f * y2);

#pragma unroll
        for (int m = 0; m < 16; m++) acc[m] = fmaf(Y[m], w, acc[m]);
    }

    // Gram matrices: ps_l[q][r] = cg_l * sum_{m in l} c[m][q] * c[m][r]
    // lane holds column r = lane. Broadcast column q via shuffles.
    float* ob = out + (size_t)node * 4096;

    for (int q = 0; q < 32; q++) {
        float cq[16];
#pragma unroll
        for (int m = 0; m < 16; m++) cq[m] = __shfl_sync(0xffffffffu, acc[m], q);

        float v0 = cq[0] * acc[0];
        float v1 = cq[1] * acc[1] + cq[2] * acc[2] + cq[3] * acc[3];
        float v2 = cq[4] * acc[4] + cq[5] * acc[5] + cq[6] * acc[6]
                 + cq[7] * acc[7] + cq[8] * acc[8];
        float v3 = cq[9] * acc[9] + cq[10] * acc[10] + cq[11] * acc[11]
                 + cq[12] * acc[12] + cq[13] * acc[13] + cq[14] * acc[14]
                 + cq[15] * acc[15];

        ob[          q * 32 + lane] = v0;                    // cg0 = 1
        ob[1024 +    q * 32 + lane] = 0.5773502691896258f * v1;  // 3^-1/2
        ob[2048 +    q * 32 + lane] = 0.4472135954999579f * v2;  // 5^-1/2
        ob[3072 +    q * 32 + lane] = 0.3779644730092272f * v3;  // 7^-1/2
    }
}

// ---------------------------------------------------------------------------
extern "C" void kernel_launch(void* const* d_in, const int* in_sizes, int n_in,
                              void* d_out, int out_size) {
    const float* positions   = (const float*)d_in[0];
    const float* cells       = (const float*)d_in[1];
    const int*   species     = (const int*)  d_in[2];
    const int*   edge_idx    = (const int*)  d_in[3];
    const int*   edge_shifts = (const int*)  d_in[4];
    const float* spec_embed  = (const float*)d_in[5];
    const float* radial_mu   = (const float*)d_in[6];
    const float* radial_sig  = (const float*)d_in[7];
    float* out = (float*)d_out;

    int N = in_sizes[0] / 3;
    int E = in_sizes[3] / 2;

    k_zero<<<(N + 255) / 256, 256>>>(N);
    k_hist<<<(E + 255) / 256, 256>>>(edge_idx, E);
    k_scan<<<1, 1024>>>(N, E);
    k_scatter<<<(E + 255) / 256, 256>>>(edge_idx, E);

    int warps_per_block = 8;                  // 256 threads
    int blocks = (N + warps_per_block - 1) / warps_per_block;
    k_main<<<blocks, 256>>>(positions, cells, species, edge_idx, edge_shifts,
                            spec_embed, radial_mu, radial_sig, out, N, E);
}

// round 2
// speedup vs baseline: 1.2722x; 1.2722x over previous
#include <cuda_runtime.h>

// Problem-size maxima (setup_inputs: N=20000, E=320000)
#define NMAX_NODES 20000
#define EMAX_EDGES 320000

// Scratch (static device globals; no allocation allowed)
__device__ int    g_count[NMAX_NODES];
__device__ int    g_off[NMAX_NODES + 1];
__device__ int    g_cur[NMAX_NODES];
__device__ float4 g_rec[EMAX_EDGES];   // per original edge: {x, y, z, r}
__device__ int    g_aux[EMAX_EDGES];   // species | (i << 2)
__device__ float4 g_srec[EMAX_EDGES];  // per sorted slot: {x, y, z, r}
__device__ int    g_ssp[EMAX_EDGES];   // per sorted slot: species

// ---------------------------------------------------------------------------
__global__ void k_zero(int N) {
    int t = blockIdx.x * blockDim.x + threadIdx.x;
    if (t < N) g_count[t] = 0;
}

// Edge-parallel: compute per-edge geometry once (coalesced, high MLP),
// histogram only edges with r < CUTOFF (others contribute exactly 0).
__global__ void __launch_bounds__(256) k_edge(
    const float* __restrict__ pos,
    const float* __restrict__ cells,
    const int*   __restrict__ species,
    const int*   __restrict__ eidx,
    const int*   __restrict__ shifts,
    int E)
{
    int e = blockIdx.x * blockDim.x + threadIdx.x;
    if (e >= E) return;

    int i = eidx[e];
    int j = eidx[E + e];

    float s0 = (float)shifts[3 * e + 0];
    float s1 = (float)shifts[3 * e + 1];
    float s2 = (float)shifts[3 * e + 2];

    float dx = pos[3 * j + 0] - pos[3 * i + 0] + s0 * cells[0] + s1 * cells[3] + s2 * cells[6];
    float dy = pos[3 * j + 1] - pos[3 * i + 1] + s0 * cells[1] + s1 * cells[4] + s2 * cells[7];
    float dz = pos[3 * j + 2] - pos[3 * i + 2] + s0 * cells[2] + s1 * cells[5] + s2 * cells[8];

    float r2   = dx * dx + dy * dy + dz * dz + 1e-12f;
    float rinv = rsqrtf(r2);
    float r    = r2 * rinv;

    g_rec[e] = make_float4(dx * rinv, dy * rinv, dz * rinv, r);
    g_aux[e] = species[j] | (i << 2);

    if (r < 5.0f) atomicAdd(&g_count[i], 1);
}

// Single-block exclusive scan over counts -> offsets (+cursor copy)
__global__ void k_scan(int N) {
    __shared__ int sh[1024];
    int t = threadIdx.x;
    int chunk = (N + 1023) >> 10;
    int b = t * chunk;
    int en = min(b + chunk, N);
    int s = 0;
    for (int k = b; k < en; k++) s += g_count[k];
    sh[t] = s;
    __syncthreads();
    for (int off = 1; off < 1024; off <<= 1) {
        int tmp = (t >= off) ? sh[t - off] : 0;
        __syncthreads();
        sh[t] += tmp;
        __syncthreads();
    }
    int base = sh[t] - s;  // exclusive prefix
    for (int k = b; k < en; k++) {
        g_off[k] = base;
        g_cur[k] = base;
        base += g_count[k];
    }
    if (t == 1023) g_off[N] = sh[1023];
}

// Scatter valid-edge records into per-node contiguous lists
__global__ void __launch_bounds__(256) k_scatter(int E) {
    int e = blockIdx.x * blockDim.x + threadIdx.x;
    if (e >= E) return;
    float4 rec = g_rec[e];
    if (rec.w < 5.0f) {
        int aux = g_aux[e];
        int i   = aux >> 2;
        int p   = atomicAdd(&g_cur[i], 1);
        g_srec[p] = rec;
        g_ssp[p]  = aux & 3;
    }
}

// ---------------------------------------------------------------------------
// One warp per node. Lane r owns accumulator column c[m][r].
// Edges are loaded cooperatively (lane k loads record k) and broadcast by shfl.
__global__ void __launch_bounds__(256) k_main(
    const float* __restrict__ embed,
    const float* __restrict__ mu,
    const float* __restrict__ sig,
    float* __restrict__ out,
    int N)
{
    int gwarp = (blockIdx.x * blockDim.x + threadIdx.x) >> 5;
    int lane  = threadIdx.x & 31;
    if (gwarp >= N) return;
    const int node = gwarp;

    float acc[16];
#pragma unroll
    for (int m = 0; m < 16; m++) acc[m] = 0.0f;

    const int   p_lane = lane >> 3;   // pseudo index 0..3
    const int   n_lane = lane & 7;    // radial index 0..7
    const float mu_l   = mu[n_lane];
    const float sg     = sig[0];
    const float negInv = -1.0f / (2.0f * sg * sg);

    // Per-lane embed candidates (select by species with predicated moves)
    const float emb0 = embed[0 * 4 + p_lane];
    const float emb1 = embed[1 * 4 + p_lane];
    const float emb2 = embed[2 * 4 + p_lane];
    const float emb3 = embed[3 * 4 + p_lane];

    const int st  = g_off[node];
    const int cnt = g_off[node + 1] - st;

    for (int b = 0; b < cnt; b += 32) {
        int mct = min(cnt - b, 32);

        float4 myrec = make_float4(0.f, 0.f, 0.f, 0.f);
        int    mysp  = 0;
        if (lane < mct) {
            myrec = g_srec[st + b + lane];
            mysp  = g_ssp[st + b + lane];
        }

        for (int k = 0; k < mct; k++) {
            float x  = __shfl_sync(0xffffffffu, myrec.x, k);
            float y  = __shfl_sync(0xffffffffu, myrec.y, k);
            float z  = __shfl_sync(0xffffffffu, myrec.z, k);
            float r  = __shfl_sync(0xffffffffu, myrec.w, k);
            int   sp = __shfl_sync(0xffffffffu, mysp,    k);

            float fc = 0.5f * (__cosf(0.6283185307f * r) + 1.0f);
            float d  = r - mu_l;
            float Rn = __expf(d * d * negInv) * fc;
            float em = (sp == 0) ? emb0 : (sp == 1) ? emb1 : (sp == 2) ? emb2 : emb3;
            float w  = em * Rn;

            float x2 = x * x, y2 = y * y, z2 = z * z;
            float Y[16];
            Y[0]  = 0.28209479177387814f;
            Y[1]  = 0.4886025119029199f * y;
            Y[2]  = 0.4886025119029199f * z;
            Y[3]  = 0.4886025119029199f * x;
            Y[4]  = 1.0925484305920792f * x * y;
            Y[5]  = 1.0925484305920792f * y * z;
            Y[6]  = 0.31539156525252005f * (3.0f * z2 - 1.0f);
            Y[7]  = 1.0925484305920792f * x * z;
            Y[8]  = 0.5462742152960396f * (x2 - y2);
            Y[9]  = 0.5900435899266435f * y * (3.0f * x2 - y2);
            Y[10] = 2.890611442640554f  * x * y * z;
            Y[11] = 0.4570457994644658f * y * (5.0f * z2 - 1.0f);
            Y[12] = 0.3731763325901154f * z * (5.0f * z2 - 3.0f);
            Y[13] = 0.4570457994644658f * x * (5.0f * z2 - 1.0f);
            Y[14] = 1.445305721320277f  * z * (x2 - y2);
            Y[15] = 0.5900435899266435f * x * (x2 - 3.0f * y2);

#pragma unroll
            for (int m = 0; m < 16; m++) acc[m] = fmaf(Y[m], w, acc[m]);
        }
    }

    // Gram matrices: ps_l[q][r] = cg_l * sum_{m in l} c[m][q] * c[m][r]
    float* ob = out + (size_t)node * 4096;

    for (int q = 0; q < 32; q++) {
        float cq[16];
#pragma unroll
        for (int m = 0; m < 16; m++) cq[m] = __shfl_sync(0xffffffffu, acc[m], q);

        float v0 = cq[0] * acc[0];
        float v1 = cq[1] * acc[1] + cq[2] * acc[2] + cq[3] * acc[3];
        float v2 = cq[4] * acc[4] + cq[5] * acc[5] + cq[6] * acc[6]
                 + cq[7] * acc[7] + cq[8] * acc[8];
        float v3 = cq[9] * acc[9] + cq[10] * acc[10] + cq[11] * acc[11]
                 + cq[12] * acc[12] + cq[13] * acc[13] + cq[14] * acc[14]
                 + cq[15] * acc[15];

        ob[          q * 32 + lane] = v0;                        // cg0 = 1
        ob[1024 +    q * 32 + lane] = 0.5773502691896258f * v1;  // 3^-1/2
        ob[2048 +    q * 32 + lane] = 0.4472135954999579f * v2;  // 5^-1/2
        ob[3072 +    q * 32 + lane] = 0.3779644730092272f * v3;  // 7^-1/2
    }
}

// ---------------------------------------------------------------------------
extern "C" void kernel_launch(void* const* d_in, const int* in_sizes, int n_in,
                              void* d_out, int out_size) {
    const float* positions   = (const float*)d_in[0];
    const float* cells       = (const float*)d_in[1];
    const int*   species     = (const int*)  d_in[2];
    const int*   edge_idx    = (const int*)  d_in[3];
    const int*   edge_shifts = (const int*)  d_in[4];
    const float* spec_embed  = (const float*)d_in[5];
    const float* radial_mu   = (const float*)d_in[6];
    const float* radial_sig  = (const float*)d_in[7];
    float* out = (float*)d_out;

    int N = in_sizes[0] / 3;
    int E = in_sizes[3] / 2;

    k_zero<<<(N + 255) / 256, 256>>>(N);
    k_edge<<<(E + 255) / 256, 256>>>(positions, cells, species, edge_idx,
                                     edge_shifts, E);
    k_scan<<<1, 1024>>>(N);
    k_scatter<<<(E + 255) / 256, 256>>>(E);

    int warps_per_block = 8;  // 256 threads
    int blocks = (N + warps_per_block - 1) / warps_per_block;
    k_main<<<blocks, 256>>>(spec_embed, radial_mu, radial_sig, out, N);
}

// round 4
// speedup vs baseline: 1.4009x; 1.1012x over previous
#include <cuda_runtime.h>

// Problem-size maxima (setup_inputs: N=20000, E=320000)
#define NMAX_NODES 20000
#define EMAX_EDGES 320000

// Scratch (static device globals; no allocation allowed)
__device__ int    g_count[NMAX_NODES];
__device__ int    g_off[NMAX_NODES + 1];
__device__ int    g_cur[NMAX_NODES];
__device__ float4 g_rec[EMAX_EDGES];   // per edge: {x, y, z, r(with species in 2 LSBs)}
__device__ int    g_aux[EMAX_EDGES];   // destination node i
__device__ float4 g_srec[EMAX_EDGES];  // sorted by destination node

// ---------------------------------------------------------------------------
__global__ void k_zero(int N) {
    int t = blockIdx.x * blockDim.x + threadIdx.x;
    if (t < N) g_count[t] = 0;
}

// Edge-parallel: compute geometry once (coalesced, high MLP); pack species
// into the 2 LSBs of r's mantissa (<= 3 ulp, harmless at 1e-3 tolerance);
// histogram only edges with r < CUTOFF (others contribute exactly 0).
__global__ void __launch_bounds__(256) k_edge(
    const float* __restrict__ pos,
    const float* __restrict__ cells,
    const int*   __restrict__ species,
    const int*   __restrict__ eidx,
    const int*   __restrict__ shifts,
    int E)
{
    int e = blockIdx.x * blockDim.x + threadIdx.x;
    if (e >= E) return;

    int i = eidx[e];
    int j = eidx[E + e];

    float s0 = (float)shifts[3 * e + 0];
    float s1 = (float)shifts[3 * e + 1];
    float s2 = (float)shifts[3 * e + 2];

    float dx = pos[3 * j + 0] - pos[3 * i + 0] + s0 * cells[0] + s1 * cells[3] + s2 * cells[6];
    float dy = pos[3 * j + 1] - pos[3 * i + 1] + s0 * cells[1] + s1 * cells[4] + s2 * cells[7];
    float dz = pos[3 * j + 2] - pos[3 * i + 2] + s0 * cells[2] + s1 * cells[5] + s2 * cells[8];

    float r2   = dx * dx + dy * dy + dz * dz + 1e-12f;
    float rinv = rsqrtf(r2);
    float r    = r2 * rinv;

    // pack species[j] into mantissa LSBs of r
    int rb = (__float_as_int(r) & ~3) | (species[j] & 3);
    float rw = __int_as_float(rb);

    g_rec[e] = make_float4(dx * rinv, dy * rinv, dz * rinv, rw);
    g_aux[e] = i;

    if (rw < 5.0f) atomicAdd(&g_count[i], 1);
}

// Single-block exclusive scan over counts -> offsets (+cursor copy)
__global__ void k_scan(int N) {
    __shared__ int sh[1024];
    int t = threadIdx.x;
    int chunk = (N + 1023) >> 10;
    int b = t * chunk;
    int en = min(b + chunk, N);
    int s = 0;
    for (int k = b; k < en; k++) s += g_count[k];
    sh[t] = s;
    __syncthreads();
    for (int off = 1; off < 1024; off <<= 1) {
        int tmp = (t >= off) ? sh[t - off] : 0;
        __syncthreads();
        sh[t] += tmp;
        __syncthreads();
    }
    int base = sh[t] - s;  // exclusive prefix
    for (int k = b; k < en; k++) {
        g_off[k] = base;
        g_cur[k] = base;
        base += g_count[k];
    }
    if (t == 1023) g_off[N] = sh[1023];
}

// Scatter valid-edge records into per-node contiguous lists
__global__ void __launch_bounds__(256) k_scatter(int E) {
    int e = blockIdx.x * blockDim.x + threadIdx.x;
    if (e >= E) return;
    float4 rec = g_rec[e];
    if (rec.w < 5.0f) {
        int p = atomicAdd(&g_cur[g_aux[e]], 1);
        g_srec[p] = rec;
    }
}

// ---------------------------------------------------------------------------
// 4 nodes per warp; 8 lanes per node; each lane owns 4 consecutive columns
// (cols = 4*lane8 .. +3) of the 16x32 accumulator. Width-8 shuffles broadcast
// edge data / Gram columns to all 4 groups simultaneously. Output written as
// coalesced float4 stores.
__global__ void __launch_bounds__(128) k_main(
    const float* __restrict__ embed,
    const float* __restrict__ mu,
    const float* __restrict__ sig,
    float* __restrict__ out,
    int N)
{
    const int lane   = threadIdx.x & 31;
    const int lane8  = lane & 7;
    const int grp    = lane >> 3;
    const int gwarp  = (blockIdx.x * blockDim.x + threadIdx.x) >> 5;
    const int node   = gwarp * 4 + grp;
    const bool active = (node < N);
    const int nodec  = active ? node : 0;

    const int st  = g_off[nodec];
    const int cnt = active ? (g_off[nodec + 1] - st) : 0;

    // lane owns columns col = 4*lane8 + c; p = col>>3 (same for all 4),
    // n = (lane8&1)*4 + c (4 consecutive radial indices)
    const int p_lane = lane8 >> 1;
    const int nb     = (lane8 & 1) * 4;
    const float mu0 = mu[nb + 0], mu1 = mu[nb + 1], mu2 = mu[nb + 2], mu3 = mu[nb + 3];
    const float sg = sig[0];
    const float negInv = -1.0f / (2.0f * sg * sg);

    const float emb0 = embed[0 * 4 + p_lane];
    const float emb1 = embed[1 * 4 + p_lane];
    const float emb2 = embed[2 * 4 + p_lane];
    const float emb3 = embed[3 * 4 + p_lane];

    float acc[16][4];
#pragma unroll
    for (int m = 0; m < 16; m++)
#pragma unroll
        for (int c = 0; c < 4; c++) acc[m][c] = 0.0f;

    // warp-uniform max edge count over the 4 groups
    int mx = cnt;
    mx = max(mx, __shfl_xor_sync(0xffffffffu, mx, 8));
    mx = max(mx, __shfl_xor_sync(0xffffffffu, mx, 16));

    for (int b = 0; b < mx; b += 8) {
        float4 rec = make_float4(0.f, 0.f, 1.f, 0.f);
        if (b + lane8 < cnt) rec = g_srec[st + b + lane8];

        int kmax = min(8, mx - b);
        for (int k = 0; k < kmax; k++) {
            float x  = __shfl_sync(0xffffffffu, rec.x, k, 8);
            float y  = __shfl_sync(0xffffffffu, rec.y, k, 8);
            float z  = __shfl_sync(0xffffffffu, rec.z, k, 8);
            float rw = __shfl_sync(0xffffffffu, rec.w, k, 8);

            int  sp    = __float_as_int(rw) & 3;
            bool valid = (b + k < cnt);

            float fc = 0.5f * (__cosf(0.6283185307f * rw) + 1.0f);
            float em = (sp & 2) ? ((sp & 1) ? emb3 : emb2)
                                : ((sp & 1) ? emb1 : emb0);
            float wk = valid ? em * fc : 0.0f;

            float d0 = rw - mu0, d1 = rw - mu1, d2 = rw - mu2, d3 = rw - mu3;
            float w[4];
            w[0] = wk * __expf(d0 * d0 * negInv);
            w[1] = wk * __expf(d1 * d1 * negInv);
            w[2] = wk * __expf(d2 * d2 * negInv);
            w[3] = wk * __expf(d3 * d3 * negInv);

            float x2 = x * x, y2 = y * y, z2 = z * z;
            float Y[16];
            Y[0]  = 0.28209479177387814f;
            Y[1]  = 0.4886025119029199f * y;
            Y[2]  = 0.4886025119029199f * z;
            Y[3]  = 0.4886025119029199f * x;
            Y[4]  = 1.0925484305920792f * x * y;
            Y[5]  = 1.0925484305920792f * y * z;
            Y[6]  = 0.31539156525252005f * (3.0f * z2 - 1.0f);
            Y[7]  = 1.0925484305920792f * x * z;
            Y[8]  = 0.5462742152960396f * (x2 - y2);
            Y[9]  = 0.5900435899266435f * y * (3.0f * x2 - y2);
            Y[10] = 2.890611442640554f  * x * y * z;
            Y[11] = 0.4570457994644658f * y * (5.0f * z2 - 1.0f);
            Y[12] = 0.3731763325901154f * z * (5.0f * z2 - 3.0f);
            Y[13] = 0.4570457994644658f * x * (5.0f * z2 - 1.0f);
            Y[14] = 1.445305721320277f  * z * (x2 - y2);
            Y[15] = 0.5900435899266435f * x * (x2 - 3.0f * y2);

#pragma unroll
            for (int m = 0; m < 16; m++)
#pragma unroll
                for (int c = 0; c < 4; c++)
                    acc[m][c] = fmaf(Y[m], w[c], acc[m][c]);
        }
    }

    // Gram: ps_l[q][r] = cg_l * sum_{m in l} c[m][q] c[m][r]; lane owns 4 r's.
    float* ob = out + (size_t)nodec * 4096 + lane8 * 4;

    for (int qb = 0; qb < 8; qb++) {
#pragma unroll
        for (int jj = 0; jj < 4; jj++) {
            int q = qb * 4 + jj;
            float cq[16];
#pragma unroll
            for (int m = 0; m < 16; m++)
                cq[m] = __shfl_sync(0xffffffffu, acc[m][jj], qb, 8);

            float v0[4], v1[4], v2[4], v3[4];
#pragma unroll
            for (int c = 0; c < 4; c++) {
                v0[c] = cq[0] * acc[0][c];
                float s1v = cq[1] * acc[1][c];
                s1v = fmaf(cq[2], acc[2][c], s1v);
                s1v = fmaf(cq[3], acc[3][c], s1v);
                v1[c] = 0.5773502691896258f * s1v;
                float s2v = cq[4] * acc[4][c];
                s2v = fmaf(cq[5], acc[5][c], s2v);
                s2v = fmaf(cq[6], acc[6][c], s2v);
                s2v = fmaf(cq[7], acc[7][c], s2v);
                s2v = fmaf(cq[8], acc[8][c], s2v);
                v2[c] = 0.4472135954999579f * s2v;
                float s3v = cq[9] * acc[9][c];
                s3v = fmaf(cq[10], acc[10][c], s3v);
                s3v = fmaf(cq[11], acc[11][c], s3v);
                s3v = fmaf(cq[12], acc[12][c], s3v);
                s3v = fmaf(cq[13], acc[13][c], s3v);
                s3v = fmaf(cq[14], acc[14][c], s3v);
                s3v = fmaf(cq[15], acc[15][c], s3v);
                v3[c] = 0.3779644730092272f * s3v;
            }

            if (active) {
                *(float4*)(ob +        q * 32) = make_float4(v0[0], v0[1], v0[2], v0[3]);
                *(float4*)(ob + 1024 + q * 32) = make_float4(v1[0], v1[1], v1[2], v1[3]);
                *(float4*)(ob + 2048 + q * 32) = make_float4(v2[0], v2[1], v2[2], v2[3]);
                *(float4*)(ob + 3072 + q * 32) = make_float4(v3[0], v3[1], v3[2], v3[3]);
            }
        }
    }
}

// ---------------------------------------------------------------------------
extern "C" void kernel_launch(void* const* d_in, const int* in_sizes, int n_in,
                              void* d_out, int out_size) {
    const float* positions   = (const float*)d_in[0];
    const float* cells       = (const float*)d_in[1];
    const int*   species     = (const int*)  d_in[2];
    const int*   edge_idx    = (const int*)  d_in[3];
    const int*   edge_shifts = (const int*)  d_in[4];
    const float* spec_embed  = (const float*)d_in[5];
    const float* radial_mu   = (const float*)d_in[6];
    const float* radial_sig  = (const float*)d_in[7];
    float* out = (float*)d_out;

    int N = in_sizes[0] / 3;
    int E = in_sizes[3] / 2;

    k_zero<<<(N + 255) / 256, 256>>>(N);
    k_edge<<<(E + 255) / 256, 256>>>(positions, cells, species, edge_idx,
                                     edge_shifts, E);
    k_scan<<<1, 1024>>>(N);
    k_scatter<<<(E + 255) / 256, 256>>>(E);

    // 128 threads = 4 warps = 16 nodes per block
    int blocks = (N + 15) / 16;
    k_main<<<blocks, 128>>>(spec_embed, radial_mu, radial_sig, out, N);
}